// round 11
// baseline (speedup 1.0000x reference)
#include <cuda_runtime.h>
#include <cuda_bf16.h>

// 3x3 median filter, zero padding, exact median of 9.
// x: (32, 3, 512, 512) fp32 -> 96 images of 512x512.
//
// Block = 128 threads = 512 cols x 8 output rows of one image (one strip).
// Thread = 4 cols x 8 rows (32 px), register-resident rolling row-pairs:
// per pair, sort2 of the two middle rows is shared by both emitted rows;
// sliding 3-wide windows share pair min/max; exact min/max network
// (~17.5 FMNMX/px). 10 input rows per strip (1.25x read amp).
// Zero-padding via clamped addresses + exact 0/1 FMUL masks (fma pipe).
// Streaming stores keep the input hot in L2.

#define W 512
#define H 512
#define NIMG 96

__device__ __forceinline__ float med3(float a, float b, float c) {
    return fmaxf(fminf(a, b), fminf(fmaxf(a, b), c));
}

// Load one row's 6-column window (cb-1 .. cb+4), clamped addresses.
template <bool MASK_ROW>
__device__ __forceinline__ void load_row(const float* __restrict__ rowp,
                                         int cb, int cl, int cr,
                                         float ml, float mr, float mrow,
                                         float* c) {
    const float4 v = *reinterpret_cast<const float4*>(rowp + cb);
    const float l = __ldg(rowp + cl);
    const float r = __ldg(rowp + cr);
    if (MASK_ROW) {
        c[0] = l * (ml * mrow);
        c[1] = v.x * mrow; c[2] = v.y * mrow;
        c[3] = v.z * mrow; c[4] = v.w * mrow;
        c[5] = r * (mr * mrow);
    } else {
        c[0] = l * ml;
        c[1] = v.x; c[2] = v.y; c[3] = v.z; c[4] = v.w;
        c[5] = r * mr;
    }
}

// Emit one output row: insert row a into (mn, mx) = sort2 of the other two
// rows, combine 3-wide windows with pair sharing, streaming-store a float4.
__device__ __forceinline__ void emit_row(const float* a, const float* mn,
                                         const float* mx,
                                         float* __restrict__ outp) {
    float lo[6], mi[6], hi[6];
    #pragma unroll
    for (int i = 0; i < 6; i++) {
        lo[i] = fminf(a[i], mn[i]);
        hi[i] = fmaxf(a[i], mx[i]);
        mi[i] = fmaxf(mn[i], fminf(a[i], mx[i]));
    }
    float o[4];
    #pragma unroll
    for (int t = 0; t < 2; t++) {
        const int i = 2 * t + 1;
        const float A = fmaxf(lo[i], lo[i + 1]);
        const float B = fminf(hi[i], hi[i + 1]);
        const float n = fminf(mi[i], mi[i + 1]);
        const float m = fmaxf(mi[i], mi[i + 1]);
        o[2 * t]     = med3(fmaxf(A, lo[2 * t]),
                            fmaxf(n, fminf(m, mi[2 * t])),
                            fminf(B, hi[2 * t]));
        o[2 * t + 1] = med3(fmaxf(A, lo[2 * t + 3]),
                            fminf(m, fmaxf(n, mi[2 * t + 3])),
                            fminf(B, hi[2 * t + 3]));
    }
    float4 res; res.x = o[0]; res.y = o[1]; res.z = o[2]; res.w = o[3];
    __stcs(reinterpret_cast<float4*>(outp), res);
}

__global__ void __launch_bounds__(128, 10)
median3x3_kernel(const float* __restrict__ x, float* __restrict__ out) {
    const int bid = blockIdx.x;
    const int cb  = threadIdx.x << 2;          // column base (0..508)
    const int y0  = (bid & 63) << 3;           // strip top output row (step 8)
    const int ibase = (bid >> 6) * (H * W);    // image base (max 24.9M)
    const float* img = x + ibase;
    float* oimg = out + ibase;

    const int cl = max(cb - 1, 0);
    const int cr = min(cb + 4, W - 1);
    const float ml = (cb > 0)     ? 1.0f : 0.0f;
    const float mr = (cb < W - 4) ? 1.0f : 0.0f;
    const float mt = (y0 > 0)     ? 1.0f : 0.0f;   // row y0-1 valid
    const float mb = (y0 < H - 8) ? 1.0f : 0.0f;   // row y0+8 valid

    float ra[6], rb[6], rc[6], rd[6], mn[6], mx[6];

    const float* ip = img + y0 * W;
    float* op = oimg + y0 * W + cb;

    // Pre-load rows y0-1 (masked) and y0.
    load_row<true >(img + max(y0 - 1, 0) * W, cb, cl, cr, ml, mr, mt, ra);
    load_row<false>(ip, cb, cl, cr, ml, mr, 1.0f, rb);

    #pragma unroll
    for (int p = 0; p < 4; p++) {
        // Load rows y0+2p+1 and y0+2p+2 (last one masked at image bottom).
        load_row<false>(ip + (2 * p + 1) * W, cb, cl, cr, ml, mr, 1.0f, rc);
        if (p < 3) {
            load_row<false>(ip + (2 * p + 2) * W, cb, cl, cr, ml, mr, 1.0f, rd);
        } else {
            load_row<true >(img + min(y0 + 8, H - 1) * W, cb, cl, cr, ml, mr, mb, rd);
        }

        // Shared sort2 of the two middle rows (rb dead after this).
        #pragma unroll
        for (int i = 0; i < 6; i++) {
            mn[i] = fminf(rb[i], rc[i]);
            mx[i] = fmaxf(rb[i], rc[i]);
        }
        emit_row(ra, mn, mx, op);              // output row y0+2p
        emit_row(rd, mn, mx, op + W);          // output row y0+2p+1
        op += 2 * W;

        // Roll: next pair's (top, m1) = (rc, rd).
        #pragma unroll
        for (int i = 0; i < 6; i++) { ra[i] = rc[i]; rb[i] = rd[i]; }
    }
}

extern "C" void kernel_launch(void* const* d_in, const int* in_sizes, int n_in,
                              void* d_out, int out_size) {
    const float* x = (const float*)d_in[0];
    float* out = (float*)d_out;

    const int grid = NIMG * (H / 8);   // 96 * 64 = 6144 strips
    median3x3_kernel<<<grid, 128>>>(x, out);
}

// round 12
// speedup vs baseline: 1.0440x; 1.0440x over previous
#include <cuda_runtime.h>
#include <cuda_bf16.h>

// 3x3 median filter, zero padding, exact median of 9.
// x: (32, 3, 512, 512) fp32 -> 96 images of 512x512.
//
// Identical algorithm/order to the round-10 best (33.8us kernel):
// thread = 4 cols x 4 output rows, register-resident, two load batches,
// shared sort2 of middle rows, pair-shared sliding-window combine,
// exact min/max network, masks on the fma pipe, streaming stores.
// Only change: 64-thread blocks with __launch_bounds__(64,20) — same
// 51-reg cap and same 40 warps/SM, but 20 independently-phased blocks
// per SM (vs 10) to de-synchronize global-load stall windows.

#define W 512
#define H 512
#define NIMG 96

__device__ __forceinline__ float med3(float a, float b, float c) {
    return fmaxf(fminf(a, b), fminf(fmaxf(a, b), c));
}

// Load one row's 6-column window (cb-1 .. cb+4), clamped addresses.
template <bool MASK_ROW>
__device__ __forceinline__ void load_row(const float* __restrict__ rowp,
                                         int cb, int cl, int cr,
                                         float ml, float mr, float mrow,
                                         float* c) {
    const float4 v = *reinterpret_cast<const float4*>(rowp + cb);
    const float l = __ldg(rowp + cl);
    const float r = __ldg(rowp + cr);
    if (MASK_ROW) {
        c[0] = l * (ml * mrow);
        c[1] = v.x * mrow; c[2] = v.y * mrow;
        c[3] = v.z * mrow; c[4] = v.w * mrow;
        c[5] = r * (mr * mrow);
    } else {
        c[0] = l * ml;
        c[1] = v.x; c[2] = v.y; c[3] = v.z; c[4] = v.w;
        c[5] = r * mr;
    }
}

// Emit one output row: insert row a into (mn, mx) = sort2 of the other two
// rows, combine 3-wide windows with pair sharing, streaming-store a float4.
__device__ __forceinline__ void emit_row(const float* a, const float* mn,
                                         const float* mx,
                                         float* __restrict__ outp) {
    float lo[6], mi[6], hi[6];
    #pragma unroll
    for (int i = 0; i < 6; i++) {
        lo[i] = fminf(a[i], mn[i]);
        hi[i] = fmaxf(a[i], mx[i]);
        mi[i] = fmaxf(mn[i], fminf(a[i], mx[i]));
    }
    float o[4];
    #pragma unroll
    for (int t = 0; t < 2; t++) {
        const int i = 2 * t + 1;
        const float A = fmaxf(lo[i], lo[i + 1]);
        const float B = fminf(hi[i], hi[i + 1]);
        const float n = fminf(mi[i], mi[i + 1]);
        const float m = fmaxf(mi[i], mi[i + 1]);
        o[2 * t]     = med3(fmaxf(A, lo[2 * t]),
                            fmaxf(n, fminf(m, mi[2 * t])),
                            fminf(B, hi[2 * t]));
        o[2 * t + 1] = med3(fmaxf(A, lo[2 * t + 3]),
                            fminf(m, fmaxf(n, mi[2 * t + 3])),
                            fminf(B, hi[2 * t + 3]));
    }
    float4 res; res.x = o[0]; res.y = o[1]; res.z = o[2]; res.w = o[3];
    __stcs(reinterpret_cast<float4*>(outp), res);
}

__global__ void __launch_bounds__(64, 20)
median3x3_kernel(const float* __restrict__ x, float* __restrict__ out) {
    const int tid = blockIdx.x * 64 + threadIdx.x;
    const int cb  = (tid & 127) << 2;          // column base (0..508)
    const int sid = tid >> 7;                  // strip id
    const int y0  = (sid & 127) << 2;          // strip top output row (step 4)
    const size_t ibase = (size_t)(sid >> 7) * (H * W);
    const float* img = x + ibase;
    float* oimg = out + ibase;

    const int cl = (cb == 0)     ? 0     : cb - 1;
    const int cr = (cb == W - 4) ? W - 1 : cb + 4;
    const float ml = (cb > 0)     ? 1.0f : 0.0f;
    const float mr = (cb < W - 4) ? 1.0f : 0.0f;

    const float mt = (y0 > 0)     ? 1.0f : 0.0f;   // row y0-1 valid
    const float mb = (y0 < H - 4) ? 1.0f : 0.0f;   // row y0+4 valid

    float ra[6], rb[6], rc[6], rd[6], re[6], rf[6];
    float mn[6], mx[6];

    // --- pair 0: output rows y0, y0+1 (inputs y0-1 .. y0+2) ---
    load_row<true >(img + (y0 > 0 ? y0 - 1 : 0) * W, cb, cl, cr, ml, mr, mt, ra);
    load_row<false>(img + (y0    ) * W, cb, cl, cr, ml, mr, 1.0f, rb);
    load_row<false>(img + (y0 + 1) * W, cb, cl, cr, ml, mr, 1.0f, rc);
    load_row<false>(img + (y0 + 2) * W, cb, cl, cr, ml, mr, 1.0f, rd);

    #pragma unroll
    for (int i = 0; i < 6; i++) {              // rb dead after this
        mn[i] = fminf(rb[i], rc[i]);
        mx[i] = fmaxf(rb[i], rc[i]);
    }
    emit_row(ra, mn, mx, oimg + (size_t)y0 * W + cb);        // ra dead
    emit_row(rd, mn, mx, oimg + (size_t)(y0 + 1) * W + cb);  // mn,mx dead

    // --- pair 1: output rows y0+2, y0+3 (inputs y0+1 .. y0+4) ---
    load_row<false>(img + (y0 + 3) * W, cb, cl, cr, ml, mr, 1.0f, re);
    load_row<true >(img + (y0 + 4 < H ? y0 + 4 : H - 1) * W, cb, cl, cr, ml, mr, mb, rf);

    #pragma unroll
    for (int i = 0; i < 6; i++) {
        mn[i] = fminf(rd[i], re[i]);
        mx[i] = fmaxf(rd[i], re[i]);
    }
    emit_row(rc, mn, mx, oimg + (size_t)(y0 + 2) * W + cb);
    emit_row(rf, mn, mx, oimg + (size_t)(y0 + 3) * W + cb);
}

extern "C" void kernel_launch(void* const* d_in, const int* in_sizes, int n_in,
                              void* d_out, int out_size) {
    const float* x = (const float*)d_in[0];
    float* out = (float*)d_out;

    const int total_threads = (NIMG * H * W) / 16;   // 1,572,864
    const int block = 64;
    const int grid = total_threads / block;           // 24576
    median3x3_kernel<<<grid, block>>>(x, out);
}